// round 13
// baseline (speedup 1.0000x reference)
#include <cuda_runtime.h>
#include <cuda_bf16.h>
#include <cstdint>

#define SLOTS  (1<<17)
#define NBUCK  (1<<16)
#define MMAX   SLOTS
#define NMAX   (1<<20)

// ---------------- device scratch (static, no allocation) ----------------
__device__ int                g_headmin[SLOTS];
__device__ int                g_rank[SLOTS];
__device__ int                g_headof[MMAX];
__device__ int                g_cluster[NMAX];
__device__ int                g_ccnt[MMAX];
__device__ int                g_coff[MMAX+1];
__device__ int                g_cpos[MMAX];
__device__ int                g_perm[NMAX];
__device__ unsigned long long g_keys_raw[MMAX];
__device__ unsigned long long g_keys_sorted[MMAX];
__device__ int                g_hist[NBUCK];
__device__ int                g_off[NBUCK];
__device__ int                g_off2[NBUCK];
__device__ __nv_bfloat16      g_Whi[256*128];     // W hi split, [c][k]
__device__ __nv_bfloat16      g_Wlo[256*128];     // W lo split, [c][k]
__device__ float              g_proj[(size_t)NMAX*256];   // cluster-sorted proj rows

// ---------------- setup ----------------
__global__ void k_init(float* __restrict__ out, int M, int N){
    int i = blockIdx.x*blockDim.x + threadIdx.x;
    if (i < SLOTS){ g_headmin[i] = 0x7fffffff; g_ccnt[i] = 0; }
    if (i < NBUCK) g_hist[i] = 0;
    size_t Ms = (size_t)M;
    if (i < 3*M) out[256*Ms + i] = 0.f;              // coord_p accumulators
    if (i < M)   out[268*Ms + (size_t)N + i] = 0.f;  // count accumulators (batch_p slot)
}

// split W into bf16 hi/lo, plain [c][k] layout
__global__ void k_wt(const float* __restrict__ W){
    int t = blockIdx.x*blockDim.x + threadIdx.x;
    if (t >= 256*128) return;
    float x = W[t];
    __nv_bfloat16 h = __float2bfloat16(x);
    __nv_bfloat16 l = __float2bfloat16(x - __bfloat162float(h));
    g_Whi[t] = h;
    g_Wlo[t] = l;
}

__global__ void k_headmin(const int* __restrict__ code0, int Npts){
    int i = blockIdx.x*blockDim.x + threadIdx.x;
    if (i >= Npts) return;
    int c0 = code0[i] >> 3;
    if (c0 >= 0 && c0 < SLOTS) atomicMin(&g_headmin[c0], i);
}

// single-block scan over slot occupancy -> g_rank, g_headof
__global__ void k_scan_slots(){
    __shared__ int ss[1024];
    int t = threadIdx.x;
    int base = t * (SLOTS/1024);
    int c = 0;
    for (int i = 0; i < SLOTS/1024; i++) c += (g_headmin[base+i] != 0x7fffffff);
    ss[t] = c; __syncthreads();
    int mycnt = c;
    for (int off = 1; off < 1024; off <<= 1){
        int v = (t >= off) ? ss[t-off] : 0;
        __syncthreads();
        ss[t] += v;
        __syncthreads();
    }
    int run = ss[t] - mycnt;
    for (int i = 0; i < SLOTS/1024; i++){
        int s = base + i;
        int h = g_headmin[s];
        if (h != 0x7fffffff){
            g_rank[s] = run;
            g_headof[run] = h;
            run++;
        }
    }
}

__global__ void k_points(const int* __restrict__ code0,
                         const float* __restrict__ coord,
                         float* __restrict__ out, int M, int Npts){
    int i = blockIdx.x*blockDim.x + threadIdx.x;
    if (i >= Npts) return;
    int c0 = code0[i] >> 3;
    int m = 0;
    if (c0 >= 0 && c0 < SLOTS) m = g_rank[c0];
    if (m < 0 || m >= MMAX) m = 0;
    g_cluster[i] = m;
    atomicAdd(&g_ccnt[m], 1);
    size_t Ms = (size_t)M;
    out[268*Ms + (size_t)i] = (float)m;              // cluster output
    if (m < M){
        atomicAdd(&out[268*Ms + (size_t)Npts + m], 1.0f);   // count
        size_t ci = 3ull*(size_t)i;
        atomicAdd(&out[256*Ms + 3*(size_t)m+0], coord[ci+0]);
        atomicAdd(&out[256*Ms + 3*(size_t)m+1], coord[ci+1]);
        atomicAdd(&out[256*Ms + 3*(size_t)m+2], coord[ci+2]);
    }
}

__global__ void k_heads(const int* __restrict__ code0,
                        const int* __restrict__ code1,
                        const int* __restrict__ grid_coord,
                        const int* __restrict__ batch,
                        float* __restrict__ out, int M, int Npts){
    int m = blockIdx.x*blockDim.x + threadIdx.x;
    if (m >= M || m >= MMAX) return;
    int h = g_headof[m];
    if (h < 0 || h >= Npts) return;
    size_t Ms = (size_t)M;
    float cf = out[268*Ms + (size_t)Npts + m];        // count (read BEFORE overwrite)
    float inv = 1.0f / cf;
    out[256*Ms + 3*(size_t)m+0] *= inv;               // coord_p = sum / count
    out[256*Ms + 3*(size_t)m+1] *= inv;
    out[256*Ms + 3*(size_t)m+2] *= inv;
    size_t hb = 3ull*(size_t)h;
    out[259*Ms + 3*(size_t)m+0] = (float)(grid_coord[hb+0] >> 1);  // grid_p
    out[259*Ms + 3*(size_t)m+1] = (float)(grid_coord[hb+1] >> 1);
    out[259*Ms + 3*(size_t)m+2] = (float)(grid_coord[hb+2] >> 1);
    int c0h = code0[h] >> 3;
    int c1h = code1[h] >> 3;
    out[262*Ms + m] = (float)c0h;                     // code_h row0
    out[263*Ms + m] = (float)c1h;                     // code_h row1
    out[264*Ms + m] = (float)m;                       // order row0 (identity)
    out[266*Ms + m] = (float)m;                       // inverse row0 (identity)
    out[268*Ms + (size_t)Npts + m] = (float)batch[h]; // batch_p (overwrites count)
    if (c1h >= 0){
        int b = c1h >> 11;                            // c1h < 2^27 -> 16-bit bucket
        if (b < NBUCK){
            g_keys_raw[m] = ((unsigned long long)(unsigned)c1h << 20) | (unsigned)m;
            atomicAdd(&g_hist[b], 1);
        }
    }
}

__global__ void k_scan_hist(){
    __shared__ int ss[1024];
    int t = threadIdx.x;
    int base = t * (NBUCK/1024);
    int c = 0;
    for (int i = 0; i < NBUCK/1024; i++) c += g_hist[base+i];
    ss[t] = c; __syncthreads();
    int mycnt = c;
    for (int off = 1; off < 1024; off <<= 1){
        int v = (t >= off) ? ss[t-off] : 0;
        __syncthreads();
        ss[t] += v;
        __syncthreads();
    }
    int run = ss[t] - mycnt;
    for (int i = 0; i < NBUCK/1024; i++){
        int s = base + i;
        g_off[s]  = run;
        g_off2[s] = run;
        run += g_hist[s];
    }
}

__global__ void k_scatter(int M){
    int m = blockIdx.x*blockDim.x + threadIdx.x;
    if (m >= M || m >= MMAX) return;
    unsigned long long key = g_keys_raw[m];
    int b = (int)(key >> 31);
    if (b < 0 || b >= NBUCK) return;
    int pos = atomicAdd(&g_off2[b], 1);
    if (pos >= 0 && pos < MMAX) g_keys_sorted[pos] = key;
}

// per-bucket insertion sort (shared staging), writes order/inverse row 1
__global__ void k_bsort(float* __restrict__ out, int M){
    __shared__ unsigned long long sb[40*128];
    int t  = blockIdx.x*128 + threadIdx.x;
    int tl = threadIdx.x;
    if (t >= NBUCK) return;
    int start = g_off[t];
    int cnt   = g_hist[t];
    if (cnt <= 0 || start < 0 || start >= MMAX) return;
    if (cnt > MMAX - start) cnt = MMAX - start;
    size_t offOrd = 265ull*(size_t)M;   // order row1
    size_t offInv = 267ull*(size_t)M;   // inverse row1
    if (cnt <= 40){
        for (int j = 0; j < cnt; j++) sb[j*128+tl] = g_keys_sorted[start+j];
        for (int a = 1; a < cnt; a++){
            unsigned long long x = sb[a*128+tl];
            int b2 = a-1;
            while (b2 >= 0 && sb[b2*128+tl] > x){ sb[(b2+1)*128+tl] = sb[b2*128+tl]; b2--; }
            sb[(b2+1)*128+tl] = x;
        }
        for (int j = 0; j < cnt; j++){
            unsigned long long key = sb[j*128+tl];
            int m = (int)(key & 0xFFFFFull);
            int p = start + j;
            if (p < M)            out[offOrd + p] = (float)m;
            if (m < M && m >= 0)  out[offInv + m] = (float)p;
        }
    } else {
        for (int a = 0; a < cnt; a++){
            int best = a; unsigned long long bk = g_keys_sorted[start+a];
            for (int j = a+1; j < cnt; j++){
                unsigned long long kj = g_keys_sorted[start+j];
                if (kj < bk){ bk = kj; best = j; }
            }
            unsigned long long tmp = g_keys_sorted[start+a];
            g_keys_sorted[start+a] = bk;
            g_keys_sorted[start+best] = tmp;
            int m = (int)(bk & 0xFFFFFull);
            if (start + a < M)    out[offOrd + start + a] = (float)m;
            if (m < M && m >= 0)  out[offInv + m] = (float)(start + a);
        }
    }
}

// exclusive scan of cluster counts -> g_coff, g_cpos
__global__ void k_scan_coff(){
    __shared__ int ss[1024];
    int t = threadIdx.x;
    int base = t * (MMAX/1024);
    int c = 0;
    for (int i = 0; i < MMAX/1024; i++) c += g_ccnt[base+i];
    ss[t] = c; __syncthreads();
    int mycnt = c;
    for (int off = 1; off < 1024; off <<= 1){
        int v = (t >= off) ? ss[t-off] : 0;
        __syncthreads();
        ss[t] += v;
        __syncthreads();
    }
    int run = ss[t] - mycnt;
    for (int i = 0; i < MMAX/1024; i++){
        int s = base + i;
        g_coff[s] = run;
        g_cpos[s] = run;
        run += g_ccnt[s];
    }
    if (t == 1023) g_coff[MMAX] = run;
}

// stable-ish scatter: perm = point indices grouped by cluster
__global__ void k_scatterp(int Npts){
    int i = blockIdx.x*blockDim.x + threadIdx.x;
    if (i >= Npts) return;
    int m = g_cluster[i];
    int pos = atomicAdd(&g_cpos[m], 1);
    if (pos >= 0 && pos < NMAX) g_perm[pos] = i;
}

// ---------------- HMMA GEMM: proj[sortedpos] = feat[perm] @ W^T + b ----------------
// mma.sync.m16n8k16 bf16, fp32 accum, 3-product split (~1e-5 precision).
// CTA: 128 sorted rows x 256 cols, 8 warps (warp tile 32x128), K chunked 4x32.
// No atomics: plain coalesced stores to g_proj.
#define SSTR 36
__device__ __forceinline__ void mma_bf16(float* d, const unsigned* a, const unsigned* b){
    asm volatile(
        "mma.sync.aligned.m16n8k16.row.col.f32.bf16.bf16.f32 "
        "{%0,%1,%2,%3}, {%4,%5,%6,%7}, {%8,%9}, {%0,%1,%2,%3};"
        : "+f"(d[0]), "+f"(d[1]), "+f"(d[2]), "+f"(d[3])
        : "r"(a[0]), "r"(a[1]), "r"(a[2]), "r"(a[3]), "r"(b[0]), "r"(b[1]));
}

__global__ __launch_bounds__(256, 1) void k_gemm_mma(const float* __restrict__ feat,
                                                     const float* __restrict__ bias,
                                                     int Npts){
    extern __shared__ char smem[];
    __nv_bfloat16* sAh = (__nv_bfloat16*)(smem);             //  9216 B
    __nv_bfloat16* sAl = (__nv_bfloat16*)(smem + 9216);      //  9216 B
    __nv_bfloat16* sBh = (__nv_bfloat16*)(smem + 18432);     // 18432 B (256c x 32k)
    __nv_bfloat16* sBl = (__nv_bfloat16*)(smem + 36864);     // 18432 B
    float*         sBias = (float*)(smem + 55296);           //  1024 B
    int*           sPerm = (int*)(smem + 56320);             //   512 B

    int tid  = threadIdx.x;
    int wid  = tid >> 5, lane = tid & 31;
    int g    = lane >> 2, tc = lane & 3;
    int row0 = blockIdx.x * 128;
    int m0w  = (wid >> 1) * 32;      // 4 warp-rows
    int n0w  = (wid & 1) * 128;      // 2 warp-cols

    if (tid < 128) sPerm[tid] = (row0 + tid < Npts) ? g_perm[row0 + tid] : 0;
    sBias[tid] = bias[tid];
    if (tid < 256 - 128){}           // (256 threads cover 256 bias entries via single store)
    // note: blockDim=256 so the single sBias[tid]=bias[tid] covers all 256.

    float acc[2][16][4];
#pragma unroll
    for (int mi = 0; mi < 2; mi++)
#pragma unroll
        for (int ni = 0; ni < 16; ni++)
#pragma unroll
            for (int q = 0; q < 4; q++) acc[mi][ni][q] = 0.f;

    for (int kc = 0; kc < 4; kc++){
        __syncthreads();
        // A chunk: 128 sorted rows x 32 k fp32 -> bf16 hi/lo
#pragma unroll
        for (int it = 0; it < 4; it++){
            int idx = tid + it*256;
            int r = idx >> 3, q = idx & 7;
            int src = sPerm[r];
            float4 f = *(const float4*)&feat[(size_t)src*128 + kc*32 + q*4];
            __nv_bfloat16 h0 = __float2bfloat16(f.x), h1 = __float2bfloat16(f.y);
            __nv_bfloat16 h2 = __float2bfloat16(f.z), h3 = __float2bfloat16(f.w);
            __nv_bfloat16 l0 = __float2bfloat16(f.x - __bfloat162float(h0));
            __nv_bfloat16 l1 = __float2bfloat16(f.y - __bfloat162float(h1));
            __nv_bfloat16 l2 = __float2bfloat16(f.z - __bfloat162float(h2));
            __nv_bfloat16 l3 = __float2bfloat16(f.w - __bfloat162float(h3));
            int base = r*SSTR + q*4;
            *(__nv_bfloat162*)&sAh[base]   = __halves2bfloat162(h0, h1);
            *(__nv_bfloat162*)&sAh[base+2] = __halves2bfloat162(h2, h3);
            *(__nv_bfloat162*)&sAl[base]   = __halves2bfloat162(l0, l1);
            *(__nv_bfloat162*)&sAl[base+2] = __halves2bfloat162(l2, l3);
        }
        // B chunk: 256 c x 32 k bf16 hi/lo
#pragma unroll
        for (int it = 0; it < 16; it++){
            int idx = tid + it*256;
            int cl = idx >> 4, pk = idx & 15;
            int src = cl*128 + kc*32 + pk*2;
            int dst = cl*SSTR + pk*2;
            *(__nv_bfloat162*)&sBh[dst] = *(const __nv_bfloat162*)&g_Whi[src];
            *(__nv_bfloat162*)&sBl[dst] = *(const __nv_bfloat162*)&g_Wlo[src];
        }
        __syncthreads();

#pragma unroll
        for (int ks = 0; ks < 2; ks++){
            int kb = ks*16;
            unsigned ah[2][4], al[2][4];
#pragma unroll
            for (int mi = 0; mi < 2; mi++){
                int rA = m0w + mi*16 + g;
                ah[mi][0] = *(const unsigned*)&sAh[rA*SSTR + kb + 2*tc];
                ah[mi][1] = *(const unsigned*)&sAh[(rA+8)*SSTR + kb + 2*tc];
                ah[mi][2] = *(const unsigned*)&sAh[rA*SSTR + kb + 2*tc + 8];
                ah[mi][3] = *(const unsigned*)&sAh[(rA+8)*SSTR + kb + 2*tc + 8];
                al[mi][0] = *(const unsigned*)&sAl[rA*SSTR + kb + 2*tc];
                al[mi][1] = *(const unsigned*)&sAl[(rA+8)*SSTR + kb + 2*tc];
                al[mi][2] = *(const unsigned*)&sAl[rA*SSTR + kb + 2*tc + 8];
                al[mi][3] = *(const unsigned*)&sAl[(rA+8)*SSTR + kb + 2*tc + 8];
            }
#pragma unroll
            for (int ni = 0; ni < 16; ni++){
                int cB = n0w + ni*8 + g;
                unsigned bh[2], bl[2];
                bh[0] = *(const unsigned*)&sBh[cB*SSTR + kb + 2*tc];
                bh[1] = *(const unsigned*)&sBh[cB*SSTR + kb + 2*tc + 8];
                bl[0] = *(const unsigned*)&sBl[cB*SSTR + kb + 2*tc];
                bl[1] = *(const unsigned*)&sBl[cB*SSTR + kb + 2*tc + 8];
#pragma unroll
                for (int mi = 0; mi < 2; mi++){
                    mma_bf16(acc[mi][ni], ah[mi], bh);   // Ah*Wh
                    mma_bf16(acc[mi][ni], al[mi], bh);   // Al*Wh
                    mma_bf16(acc[mi][ni], ah[mi], bl);   // Ah*Wl
                }
            }
        }
    }

    // epilogue: plain stores of proj+bias (coalesced, no atomics)
#pragma unroll
    for (int mi = 0; mi < 2; mi++){
        int r1 = row0 + m0w + mi*16 + g;
        int r2 = r1 + 8;
#pragma unroll
        for (int ni = 0; ni < 16; ni++){
            int c0 = n0w + ni*8 + 2*tc;
            float b0 = sBias[c0], b1 = sBias[c0+1];
            if (r1 < Npts){
                float2 v = make_float2(acc[mi][ni][0] + b0, acc[mi][ni][1] + b1);
                *(float2*)&g_proj[(size_t)r1*256 + c0] = v;
            }
            if (r2 < Npts){
                float2 v = make_float2(acc[mi][ni][2] + b0, acc[mi][ni][3] + b1);
                *(float2*)&g_proj[(size_t)r2*256 + c0] = v;
            }
        }
    }
}

// ---------------- fused segment-max + LayerNorm + GELU ----------------
// one warp per cluster: contiguous run [coff[m], coff[m+1]) of proj rows.
__global__ void k_segln(float* __restrict__ out,
                        const float* __restrict__ gamma,
                        const float* __restrict__ beta, int M, int Npts){
    int w = threadIdx.x >> 5, lane = threadIdx.x & 31;
    int m = blockIdx.x*8 + w;
    if (m >= M) return;
    int s = g_coff[m];
    int e = g_coff[m+1];
    if (e > Npts) e = Npts;
    float v[8];
#pragma unroll
    for (int j = 0; j < 8; j++) v[j] = -3.402823466e38f;
    for (int r = s; r < e; r++){
        const float4* p = (const float4*)(g_proj + (size_t)r*256 + lane*8);
        float4 a = p[0], b = p[1];
        v[0] = fmaxf(v[0], a.x); v[1] = fmaxf(v[1], a.y);
        v[2] = fmaxf(v[2], a.z); v[3] = fmaxf(v[3], a.w);
        v[4] = fmaxf(v[4], b.x); v[5] = fmaxf(v[5], b.y);
        v[6] = fmaxf(v[6], b.z); v[7] = fmaxf(v[7], b.w);
    }
    float sum = 0.f;
#pragma unroll
    for (int j = 0; j < 8; j++) sum += v[j];
#pragma unroll
    for (int o = 16; o; o >>= 1) sum += __shfl_xor_sync(0xffffffffu, sum, o);
    float mu = sum * (1.f/256.f);
    float q = 0.f;
#pragma unroll
    for (int j = 0; j < 8; j++){ float d = v[j]-mu; q += d*d; }
#pragma unroll
    for (int o = 16; o; o >>= 1) q += __shfl_xor_sync(0xffffffffu, q, o);
    float inv = rsqrtf(q*(1.f/256.f) + 1e-5f);
    float r8[8];
#pragma unroll
    for (int j = 0; j < 8; j++){
        int c = lane*8 + j;
        float y = (v[j]-mu)*inv*gamma[c] + beta[c];
        r8[j] = 0.5f*y*(1.f + erff(y*0.70710678118654752f));
    }
    float4* dst = (float4*)(out + (size_t)m*256 + lane*8);
    dst[0] = make_float4(r8[0], r8[1], r8[2], r8[3]);
    dst[1] = make_float4(r8[4], r8[5], r8[6], r8[7]);
}

// ---------------- launch ----------------
extern "C" void kernel_launch(void* const* d_in, const int* in_sizes, int n_in,
                              void* d_out, int out_size){
    const float* feat  = (const float*)d_in[0];
    const float* coord = (const float*)d_in[1];
    const int*   gridc = (const int*)d_in[2];
    const int*   scode = (const int*)d_in[3];    // int32 (JAX x64-disabled truncation)
    const int*   batch = (const int*)d_in[4];
    int iW = 6;
    for (int i = 5; i < n_in; i++) if (in_sizes[i] == 256*128){ iW = i; break; }
    const float* W     = (const float*)d_in[iW];
    const float* bias  = (const float*)d_in[iW+1];
    const float* gamma = (const float*)d_in[iW+2];
    const float* beta  = (const float*)d_in[iW+3];

    int N = in_sizes[0] / 128;
    int M = (out_size - N) / 269;
    float* out = (float*)d_out;
    const int* code0 = scode;
    const int* code1 = scode + N;

    const int GEMM_SMEM = 56832;
    cudaFuncSetAttribute(k_gemm_mma, cudaFuncAttributeMaxDynamicSharedMemorySize, GEMM_SMEM);

    int Tinit = 3*M > SLOTS ? 3*M : SLOTS;
    k_init<<<(Tinit+255)/256, 256>>>(out, M, N);
    k_wt<<<128, 256>>>(W);
    k_headmin<<<(N+255)/256, 256>>>(code0, N);
    k_scan_slots<<<1, 1024>>>();
    k_points<<<(N+255)/256, 256>>>(code0, coord, out, M, N);
    k_heads<<<(M+255)/256, 256>>>(code0, code1, gridc, batch, out, M, N);
    k_scan_hist<<<1, 1024>>>();
    k_scatter<<<(M+255)/256, 256>>>(M);
    k_bsort<<<NBUCK/128, 128>>>(out, M);
    k_scan_coff<<<1, 1024>>>();
    k_scatterp<<<(N+255)/256, 256>>>(N);
    k_gemm_mma<<<(N+127)/128, 256, GEMM_SMEM>>>(feat, bias, N);
    k_segln<<<(M+7)/8, 256>>>(out, gamma, beta, M, N);
}

// round 14
// speedup vs baseline: 2.0164x; 2.0164x over previous
#include <cuda_runtime.h>
#include <cuda_bf16.h>
#include <cstdint>

#define SLOTS  (1<<17)
#define NBUCK  (1<<16)
#define MMAX   SLOTS
#define NMAX   (1<<20)

// ---------------- device scratch (static, no allocation) ----------------
__device__ int                g_headmin[SLOTS];
__device__ int                g_rank[SLOTS];
__device__ int                g_headof[MMAX];
__device__ int                g_cluster[NMAX];
__device__ unsigned long long g_keys_raw[MMAX];
__device__ unsigned long long g_keys_sorted[MMAX];
__device__ int                g_hist[NBUCK];
__device__ int                g_off[NBUCK];
__device__ int                g_off2[NBUCK];
__device__ int                g_bsumA[512];
__device__ int                g_boffA[512];
__device__ int                g_bsumB[256];
__device__ int                g_boffB[256];
__device__ __nv_bfloat16      g_Whi[256*128];     // W hi split, [c][k]
__device__ __nv_bfloat16      g_Wlo[256*128];     // W lo split, [c][k]

// order-preserving float<->uint encode (total order, works for negatives)
__device__ __forceinline__ unsigned int encf(float f){
    unsigned int b = __float_as_uint(f);
    return (b & 0x80000000u) ? ~b : (b | 0x80000000u);
}
__device__ __forceinline__ float decf(unsigned int e){
    unsigned int b = (e & 0x80000000u) ? (e & 0x7FFFFFFFu) : ~e;
    return __uint_as_float(b);
}

// ---------------- setup ----------------
__global__ void k_init(float* __restrict__ out, int M, int N){
    int i = blockIdx.x*blockDim.x + threadIdx.x;
    if (i < SLOTS) g_headmin[i] = 0x7fffffff;
    if (i < NBUCK) g_hist[i] = 0;
    size_t Ms = (size_t)M;
    if (i < 3*M) out[256*Ms + i] = 0.f;              // coord_p accumulators
    if (i < M)   out[268*Ms + (size_t)N + i] = 0.f;  // count accumulators (batch_p slot)
}

// zero x region [0, 256*M) floats (encoded 0 sorts below all finite)
__global__ void k_zerox(uint4* __restrict__ x, size_t n4){
    size_t i = (size_t)blockIdx.x*blockDim.x + threadIdx.x;
    size_t stride = (size_t)gridDim.x*blockDim.x;
    uint4 z = make_uint4(0u,0u,0u,0u);
    for (; i < n4; i += stride) x[i] = z;
}

// split W into bf16 hi/lo, plain [c][k] layout
__global__ void k_wt(const float* __restrict__ W){
    int t = blockIdx.x*blockDim.x + threadIdx.x;
    if (t >= 256*128) return;
    float x = W[t];
    __nv_bfloat16 h = __float2bfloat16(x);
    __nv_bfloat16 l = __float2bfloat16(x - __bfloat162float(h));
    g_Whi[t] = h;
    g_Wlo[t] = l;
}

__global__ void k_headmin(const int* __restrict__ code0, int Npts){
    int i = blockIdx.x*blockDim.x + threadIdx.x;
    if (i >= Npts) return;
    int c0 = code0[i] >> 3;
    if (c0 >= 0 && c0 < SLOTS) atomicMin(&g_headmin[c0], i);
}

// ---------------- hierarchical scans ----------------
__global__ void k_scanA_slots(){
    __shared__ int ss[256];
    int t = threadIdx.x;
    int i = blockIdx.x*256 + t;
    ss[t] = (g_headmin[i] != 0x7fffffff) ? 1 : 0;
    __syncthreads();
    for (int o = 128; o; o >>= 1){
        if (t < o) ss[t] += ss[t+o];
        __syncthreads();
    }
    if (t == 0) g_bsumA[blockIdx.x] = ss[0];
}
__global__ void k_scanMid(int* __restrict__ bsum, int* __restrict__ boff, int n){
    __shared__ int ss[512];
    int t = threadIdx.x;
    int v = (t < n) ? bsum[t] : 0;
    ss[t] = v; __syncthreads();
    int my = v;
    for (int o = 1; o < 512; o <<= 1){
        int u = (t >= o) ? ss[t-o] : 0;
        __syncthreads();
        ss[t] += u;
        __syncthreads();
    }
    if (t < n) boff[t] = ss[t] - my;
}
__global__ void k_scanC_slots(){
    __shared__ int ss[256];
    int t = threadIdx.x;
    int i = blockIdx.x*256 + t;
    int h = g_headmin[i];
    int v = (h != 0x7fffffff) ? 1 : 0;
    ss[t] = v; __syncthreads();
    int my = v;
    for (int o = 1; o < 256; o <<= 1){
        int u = (t >= o) ? ss[t-o] : 0;
        __syncthreads();
        ss[t] += u;
        __syncthreads();
    }
    int r = ss[t] - my + g_boffA[blockIdx.x];
    if (v){
        g_rank[i] = r;
        g_headof[r] = h;
    }
}
__global__ void k_scanA_hist(){
    __shared__ int ss[256];
    int t = threadIdx.x;
    int i = blockIdx.x*256 + t;
    ss[t] = g_hist[i];
    __syncthreads();
    for (int o = 128; o; o >>= 1){
        if (t < o) ss[t] += ss[t+o];
        __syncthreads();
    }
    if (t == 0) g_bsumB[blockIdx.x] = ss[0];
}
__global__ void k_scanC_hist(){
    __shared__ int ss[256];
    int t = threadIdx.x;
    int i = blockIdx.x*256 + t;
    int v = g_hist[i];
    ss[t] = v; __syncthreads();
    int my = v;
    for (int o = 1; o < 256; o <<= 1){
        int u = (t >= o) ? ss[t-o] : 0;
        __syncthreads();
        ss[t] += u;
        __syncthreads();
    }
    int r = ss[t] - my + g_boffB[blockIdx.x];
    g_off[i]  = r;
    g_off2[i] = r;
}

__global__ void k_points(const int* __restrict__ code0,
                         const float* __restrict__ coord,
                         float* __restrict__ out, int M, int Npts){
    int i = blockIdx.x*blockDim.x + threadIdx.x;
    if (i >= Npts) return;
    int c0 = code0[i] >> 3;
    int m = 0;
    if (c0 >= 0 && c0 < SLOTS) m = g_rank[c0];
    if (m < 0 || m >= MMAX) m = 0;
    g_cluster[i] = m;
    size_t Ms = (size_t)M;
    out[268*Ms + (size_t)i] = (float)m;              // cluster output
    if (m < M){
        atomicAdd(&out[268*Ms + (size_t)Npts + m], 1.0f);   // count
        size_t ci = 3ull*(size_t)i;
        atomicAdd(&out[256*Ms + 3*(size_t)m+0], coord[ci+0]);
        atomicAdd(&out[256*Ms + 3*(size_t)m+1], coord[ci+1]);
        atomicAdd(&out[256*Ms + 3*(size_t)m+2], coord[ci+2]);
    }
}

__global__ void k_heads(const int* __restrict__ code0,
                        const int* __restrict__ code1,
                        const int* __restrict__ grid_coord,
                        const int* __restrict__ batch,
                        float* __restrict__ out, int M, int Npts){
    int m = blockIdx.x*blockDim.x + threadIdx.x;
    if (m >= M || m >= MMAX) return;
    int h = g_headof[m];
    if (h < 0 || h >= Npts) return;
    size_t Ms = (size_t)M;
    float cf = out[268*Ms + (size_t)Npts + m];        // count (read BEFORE overwrite)
    float inv = 1.0f / cf;
    out[256*Ms + 3*(size_t)m+0] *= inv;               // coord_p = sum / count
    out[256*Ms + 3*(size_t)m+1] *= inv;
    out[256*Ms + 3*(size_t)m+2] *= inv;
    size_t hb = 3ull*(size_t)h;
    out[259*Ms + 3*(size_t)m+0] = (float)(grid_coord[hb+0] >> 1);  // grid_p
    out[259*Ms + 3*(size_t)m+1] = (float)(grid_coord[hb+1] >> 1);
    out[259*Ms + 3*(size_t)m+2] = (float)(grid_coord[hb+2] >> 1);
    int c0h = code0[h] >> 3;
    int c1h = code1[h] >> 3;
    out[262*Ms + m] = (float)c0h;                     // code_h row0
    out[263*Ms + m] = (float)c1h;                     // code_h row1
    out[264*Ms + m] = (float)m;                       // order row0 (identity)
    out[266*Ms + m] = (float)m;                       // inverse row0 (identity)
    out[268*Ms + (size_t)Npts + m] = (float)batch[h]; // batch_p (overwrites count)
    if (c1h >= 0){
        int b = c1h >> 11;                            // c1h < 2^27 -> 16-bit bucket
        if (b < NBUCK){
            g_keys_raw[m] = ((unsigned long long)(unsigned)c1h << 20) | (unsigned)m;
            atomicAdd(&g_hist[b], 1);
        }
    }
}

__global__ void k_scatter(int M){
    int m = blockIdx.x*blockDim.x + threadIdx.x;
    if (m >= M || m >= MMAX) return;
    unsigned long long key = g_keys_raw[m];
    int b = (int)(key >> 31);
    if (b < 0 || b >= NBUCK) return;
    int pos = atomicAdd(&g_off2[b], 1);
    if (pos >= 0 && pos < MMAX) g_keys_sorted[pos] = key;
}

// per-bucket insertion sort (shared staging), writes order/inverse row 1
__global__ void k_bsort(float* __restrict__ out, int M){
    __shared__ unsigned long long sb[40*128];
    int t  = blockIdx.x*128 + threadIdx.x;
    int tl = threadIdx.x;
    if (t >= NBUCK) return;
    int start = g_off[t];
    int cnt   = g_hist[t];
    if (cnt <= 0 || start < 0 || start >= MMAX) return;
    if (cnt > MMAX - start) cnt = MMAX - start;
    size_t offOrd = 265ull*(size_t)M;   // order row1
    size_t offInv = 267ull*(size_t)M;   // inverse row1
    if (cnt <= 40){
        for (int j = 0; j < cnt; j++) sb[j*128+tl] = g_keys_sorted[start+j];
        for (int a = 1; a < cnt; a++){
            unsigned long long x = sb[a*128+tl];
            int b2 = a-1;
            while (b2 >= 0 && sb[b2*128+tl] > x){ sb[(b2+1)*128+tl] = sb[b2*128+tl]; b2--; }
            sb[(b2+1)*128+tl] = x;
        }
        for (int j = 0; j < cnt; j++){
            unsigned long long key = sb[j*128+tl];
            int m = (int)(key & 0xFFFFFull);
            int p = start + j;
            if (p < M)            out[offOrd + p] = (float)m;
            if (m < M && m >= 0)  out[offInv + m] = (float)p;
        }
    } else {
        for (int a = 0; a < cnt; a++){
            int best = a; unsigned long long bk = g_keys_sorted[start+a];
            for (int j = a+1; j < cnt; j++){
                unsigned long long kj = g_keys_sorted[start+j];
                if (kj < bk){ bk = kj; best = j; }
            }
            unsigned long long tmp = g_keys_sorted[start+a];
            g_keys_sorted[start+a] = bk;
            g_keys_sorted[start+best] = tmp;
            int m = (int)(bk & 0xFFFFFull);
            if (start + a < M)    out[offOrd + start + a] = (float)m;
            if (m < M && m >= 0)  out[offInv + m] = (float)(start + a);
        }
    }
}

// ---------------- HMMA GEMM (proj = feat @ W^T + b) + segment-max ----------------
#define SSTR 36
__device__ __forceinline__ void mma_bf16(float* d, const unsigned* a, const unsigned* b){
    asm volatile(
        "mma.sync.aligned.m16n8k16.row.col.f32.bf16.bf16.f32 "
        "{%0,%1,%2,%3}, {%4,%5,%6,%7}, {%8,%9}, {%0,%1,%2,%3};"
        : "+f"(d[0]), "+f"(d[1]), "+f"(d[2]), "+f"(d[3])
        : "r"(a[0]), "r"(a[1]), "r"(a[2]), "r"(a[3]), "r"(b[0]), "r"(b[1]));
}

__global__ __launch_bounds__(256, 1) void k_gemm_mma(const float* __restrict__ feat,
                                                     const float* __restrict__ bias,
                                                     unsigned int* __restrict__ xenc,
                                                     int M, int Npts){
    extern __shared__ char smem[];
    __nv_bfloat16* sAh = (__nv_bfloat16*)(smem);             //  9216 B
    __nv_bfloat16* sAl = (__nv_bfloat16*)(smem + 9216);      //  9216 B
    __nv_bfloat16* sBh = (__nv_bfloat16*)(smem + 18432);     // 18432 B
    __nv_bfloat16* sBl = (__nv_bfloat16*)(smem + 36864);     // 18432 B
    float*         sBias = (float*)(smem + 55296);           //  1024 B

    int tid  = threadIdx.x;
    int wid  = tid >> 5, lane = tid & 31;
    int g    = lane >> 2, tc = lane & 3;
    int row0 = blockIdx.x * 128;
    int m0w  = (wid >> 1) * 32;
    int n0w  = (wid & 1) * 128;

    sBias[tid] = bias[tid];

    float acc[2][16][4];
#pragma unroll
    for (int mi = 0; mi < 2; mi++)
#pragma unroll
        for (int ni = 0; ni < 16; ni++)
#pragma unroll
            for (int q = 0; q < 4; q++) acc[mi][ni][q] = 0.f;

    for (int kc = 0; kc < 4; kc++){
        __syncthreads();
#pragma unroll
        for (int it = 0; it < 4; it++){
            int idx = tid + it*256;
            int r = idx >> 3, q = idx & 7;
            float4 f = *(const float4*)&feat[(size_t)(row0 + r)*128 + kc*32 + q*4];
            __nv_bfloat16 h0 = __float2bfloat16(f.x), h1 = __float2bfloat16(f.y);
            __nv_bfloat16 h2 = __float2bfloat16(f.z), h3 = __float2bfloat16(f.w);
            __nv_bfloat16 l0 = __float2bfloat16(f.x - __bfloat162float(h0));
            __nv_bfloat16 l1 = __float2bfloat16(f.y - __bfloat162float(h1));
            __nv_bfloat16 l2 = __float2bfloat16(f.z - __bfloat162float(h2));
            __nv_bfloat16 l3 = __float2bfloat16(f.w - __bfloat162float(h3));
            int base = r*SSTR + q*4;
            *(__nv_bfloat162*)&sAh[base]   = __halves2bfloat162(h0, h1);
            *(__nv_bfloat162*)&sAh[base+2] = __halves2bfloat162(h2, h3);
            *(__nv_bfloat162*)&sAl[base]   = __halves2bfloat162(l0, l1);
            *(__nv_bfloat162*)&sAl[base+2] = __halves2bfloat162(l2, l3);
        }
#pragma unroll
        for (int it = 0; it < 16; it++){
            int idx = tid + it*256;
            int cl = idx >> 4, pk = idx & 15;
            int src = cl*128 + kc*32 + pk*2;
            int dst = cl*SSTR + pk*2;
            *(__nv_bfloat162*)&sBh[dst] = *(const __nv_bfloat162*)&g_Whi[src];
            *(__nv_bfloat162*)&sBl[dst] = *(const __nv_bfloat162*)&g_Wlo[src];
        }
        __syncthreads();

#pragma unroll
        for (int ks = 0; ks < 2; ks++){
            int kb = ks*16;
            unsigned ah[2][4], al[2][4];
#pragma unroll
            for (int mi = 0; mi < 2; mi++){
                int rA = m0w + mi*16 + g;
                ah[mi][0] = *(const unsigned*)&sAh[rA*SSTR + kb + 2*tc];
                ah[mi][1] = *(const unsigned*)&sAh[(rA+8)*SSTR + kb + 2*tc];
                ah[mi][2] = *(const unsigned*)&sAh[rA*SSTR + kb + 2*tc + 8];
                ah[mi][3] = *(const unsigned*)&sAh[(rA+8)*SSTR + kb + 2*tc + 8];
                al[mi][0] = *(const unsigned*)&sAl[rA*SSTR + kb + 2*tc];
                al[mi][1] = *(const unsigned*)&sAl[(rA+8)*SSTR + kb + 2*tc];
                al[mi][2] = *(const unsigned*)&sAl[rA*SSTR + kb + 2*tc + 8];
                al[mi][3] = *(const unsigned*)&sAl[(rA+8)*SSTR + kb + 2*tc + 8];
            }
#pragma unroll
            for (int ni = 0; ni < 16; ni++){
                int cB = n0w + ni*8 + g;
                unsigned bh[2], bl[2];
                bh[0] = *(const unsigned*)&sBh[cB*SSTR + kb + 2*tc];
                bh[1] = *(const unsigned*)&sBh[cB*SSTR + kb + 2*tc + 8];
                bl[0] = *(const unsigned*)&sBl[cB*SSTR + kb + 2*tc];
                bl[1] = *(const unsigned*)&sBl[cB*SSTR + kb + 2*tc + 8];
#pragma unroll
                for (int mi = 0; mi < 2; mi++){
                    mma_bf16(acc[mi][ni], ah[mi], bh);
                    mma_bf16(acc[mi][ni], al[mi], bh);
                    mma_bf16(acc[mi][ni], ah[mi], bl);
                }
            }
        }
    }

#pragma unroll
    for (int mi = 0; mi < 2; mi++){
        int r1 = row0 + m0w + mi*16 + g;
        int r2 = r1 + 8;
        int m1 = (r1 < Npts) ? g_cluster[r1] : -1;
        int m2 = (r2 < Npts) ? g_cluster[r2] : -1;
        bool ok1 = (m1 >= 0 && m1 < M), ok2 = (m2 >= 0 && m2 < M);
        unsigned int* p1 = ok1 ? (xenc + (size_t)m1*256) : xenc;
        unsigned int* p2 = ok2 ? (xenc + (size_t)m2*256) : xenc;
#pragma unroll
        for (int ni = 0; ni < 16; ni++){
            int c0 = n0w + ni*8 + 2*tc;
            float b0 = sBias[c0], b1 = sBias[c0+1];
            if (ok1){
                atomicMax(p1 + c0,     encf(acc[mi][ni][0] + b0));
                atomicMax(p1 + c0 + 1, encf(acc[mi][ni][1] + b1));
            }
            if (ok2){
                atomicMax(p2 + c0,     encf(acc[mi][ni][2] + b0));
                atomicMax(p2 + c0 + 1, encf(acc[mi][ni][3] + b1));
            }
        }
    }
}

// ---------------- LayerNorm + exact GELU, in place over x region ----------------
__global__ void k_ln(float* __restrict__ out,
                     const float* __restrict__ gamma,
                     const float* __restrict__ beta, int M){
    int w = threadIdx.x >> 5, lane = threadIdx.x & 31;
    int m = blockIdx.x*8 + w;
    if (m >= M) return;
    const unsigned int* src = (const unsigned int*)out + (size_t)m*256;
    float v[8]; float s = 0.f;
#pragma unroll
    for (int j = 0; j < 8; j++){ v[j] = decf(src[lane + 32*j]); s += v[j]; }
#pragma unroll
    for (int o = 16; o; o >>= 1) s += __shfl_xor_sync(0xffffffffu, s, o);
    float mu = s * (1.f/256.f);
    float q = 0.f;
#pragma unroll
    for (int j = 0; j < 8; j++){ float d = v[j]-mu; q += d*d; }
#pragma unroll
    for (int o = 16; o; o >>= 1) q += __shfl_xor_sync(0xffffffffu, q, o);
    float inv = rsqrtf(q*(1.f/256.f) + 1e-5f);
#pragma unroll
    for (int j = 0; j < 8; j++){
        int c = lane + 32*j;
        float y = (v[j]-mu)*inv*gamma[c] + beta[c];
        out[(size_t)m*256 + c] = 0.5f*y*(1.f + erff(y*0.70710678118654752f));
    }
}

// ---------------- launch ----------------
extern "C" void kernel_launch(void* const* d_in, const int* in_sizes, int n_in,
                              void* d_out, int out_size){
    const float* feat  = (const float*)d_in[0];
    const float* coord = (const float*)d_in[1];
    const int*   gridc = (const int*)d_in[2];
    const int*   scode = (const int*)d_in[3];    // int32 (JAX x64-disabled truncation)
    const int*   batch = (const int*)d_in[4];
    int iW = 6;
    for (int i = 5; i < n_in; i++) if (in_sizes[i] == 256*128){ iW = i; break; }
    const float* W     = (const float*)d_in[iW];
    const float* bias  = (const float*)d_in[iW+1];
    const float* gamma = (const float*)d_in[iW+2];
    const float* beta  = (const float*)d_in[iW+3];

    int N = in_sizes[0] / 128;
    int M = (out_size - N) / 269;
    float* out = (float*)d_out;
    const int* code0 = scode;
    const int* code1 = scode + N;

    const int GEMM_SMEM = 56320;
    cudaFuncSetAttribute(k_gemm_mma, cudaFuncAttributeMaxDynamicSharedMemorySize, GEMM_SMEM);

    int* bsumA = nullptr; int* boffA = nullptr; int* bsumB = nullptr; int* boffB = nullptr;
    cudaGetSymbolAddress((void**)&bsumA, g_bsumA);
    cudaGetSymbolAddress((void**)&boffA, g_boffA);
    cudaGetSymbolAddress((void**)&bsumB, g_bsumB);
    cudaGetSymbolAddress((void**)&boffB, g_boffB);

    int Tinit = 3*M > SLOTS ? 3*M : SLOTS;
    k_init<<<(Tinit+255)/256, 256>>>(out, M, N);
    k_zerox<<<2048, 256>>>((uint4*)d_out, (size_t)M*64);
    k_wt<<<128, 256>>>(W);
    k_headmin<<<(N+255)/256, 256>>>(code0, N);
    k_scanA_slots<<<512, 256>>>();
    k_scanMid<<<1, 512>>>(bsumA, boffA, 512);
    k_scanC_slots<<<512, 256>>>();
    k_points<<<(N+255)/256, 256>>>(code0, coord, out, M, N);
    k_heads<<<(M+255)/256, 256>>>(code0, code1, gridc, batch, out, M, N);
    k_scanA_hist<<<256, 256>>>();
    k_scanMid<<<1, 512>>>(bsumB, boffB, 256);
    k_scanC_hist<<<256, 256>>>();
    k_scatter<<<(M+255)/256, 256>>>(M);
    k_bsort<<<NBUCK/128, 128>>>(out, M);
    k_gemm_mma<<<(N+127)/128, 256, GEMM_SMEM>>>(feat, bias, (unsigned int*)d_out, M, N);
    k_ln<<<(M+7)/8, 256>>>(out, gamma, beta, M);
}